// round 17
// baseline (speedup 1.0000x reference)
#include <cuda_runtime.h>
#include <math.h>

#define Bv   64
#define Tv   256
#define Hv   1024
#define Sv   128
#define OBSv 1024
#define ACTv 32
#define NBLK 148
#define NTHR 1024
#define KC   128
#define XST  132
#define RST  17
typedef unsigned long long ull;

__device__ __align__(16) float g_h[2][Bv * Hv];
__device__ __align__(16) float g_z[Bv * Sv];
__device__ __align__(16) float g_a1[Bv * 512];
__device__ __align__(16) float g_a2[Bv * 1024];
__device__ unsigned int g_barc;
__device__ volatile unsigned int g_barg;

__device__ __forceinline__ void ffma2(ull& a, ull x, ull w) {
    asm("fma.rn.f32x2 %0, %1, %2, %0;" : "+l"(a) : "l"(x), "l"(w));
}
__device__ __forceinline__ float foldu(ull a) {
    float x, y; asm("mov.b64 {%0, %1}, %2;" : "=f"(x), "=f"(y) : "l"(a));
    return x + y;
}
__device__ __forceinline__ float sigm(float x) { return 1.f / (1.f + expf(-x)); }
__device__ __forceinline__ float sftp(float x) { return (x > 20.f) ? x : log1pf(expf(x)); }

// cp.async.cg: L2 path (L1-bypass) -> coherent for device-written data too
__device__ __forceinline__ void cpacg(float* dst, const float* src) {
    unsigned int d = (unsigned int)__cvta_generic_to_shared(dst);
    asm volatile("cp.async.cg.shared.global [%0], [%1], 16;" :: "r"(d), "l"(src));
}
#define CPCOMMIT() asm volatile("cp.async.commit_group;")
#define CPWAIT1()  asm volatile("cp.async.wait_group 1;")

__device__ __forceinline__ void gridbar() {
    __threadfence();
    __syncthreads();
    if (threadIdx.x == 0) {
        unsigned int my = g_barg;
        if (atomicAdd(&g_barc, 1u) == NBLK - 1u) {
            g_barc = 0u; __threadfence(); g_barg = my + 1u;
        } else {
            while (g_barg == my) __nanosleep(64);
            __threadfence();
        }
    }
    __syncthreads();
}

// smem floats: 3 stages x (x 8448 + w 2688) = 33408 | nx 7616 | keep 64 | ex 128
#define STGF   11136
#define OFF_NX 33408
#define OFF_KP 41024
#define OFF_EX 41088
#define SMEM_BYTES (41216 * 4)

__global__ void __launch_bounds__(NTHR, 1)
rssm_kernel(const float* __restrict__ obs, const float* __restrict__ action,
            const unsigned char* __restrict__ resets, const float* __restrict__ noise,
            const float* __restrict__ w_ih, const float* __restrict__ w_hh,
            const float* __restrict__ b_ih, const float* __restrict__ b_hh,
            const float* __restrict__ pw1, const float* __restrict__ pb1,
            const float* __restrict__ pw2, const float* __restrict__ pb2,
            const float* __restrict__ qw1, const float* __restrict__ qb1,
            const float* __restrict__ qw2, const float* __restrict__ qb2,
            float* __restrict__ out)
{
    extern __shared__ __align__(16) float sm[];
    float* s_nx   = sm + OFF_NX;
    float* s_keep = sm + OFF_KP;
    float* s_ex   = sm + OFF_EX;
    float* s_red  = sm;                         // aliases stages 0,1 (22272 fl)

    const int tid = threadIdx.x, bid = blockIdx.x;
    const int bl = tid & 63, sg = tid >> 6;     // 64 batch lanes x 16 K-segs
    const int xr = tid >> 5;                    // x staging row (0..31; +32)
    const int xc = (tid & 31) * 4;
    const int ab = tid >> 3;                    // action staging (tid<512)
    const int aq = (tid & 7) * 4;

    float* o_pm = out;
    float* o_ps = out + (size_t)1 * Bv * Sv * Tv;
    float* o_qm = out + (size_t)2 * Bv * Sv * Tv;
    float* o_qs = out + (size_t)3 * Bv * Sv * Tv;
    float* o_h  = out + (size_t)4 * Bv * Sv * Tv;
    float* o_z  = o_h + (size_t)Bv * Tv * Hv;

    for (int i = bid * NTHR + tid; i < Bv * Hv; i += NBLK * NTHR) g_h[0][i] = 0.f;
    for (int i = bid * NTHR + tid; i < Bv * Sv; i += NBLK * NTHR) g_z[i] = 0.f;
    if (tid < Bv) s_keep[tid] = resets[tid] ? 0.f : 1.f;
    gridbar();

    for (int t = 0; t < Tv; ++t) {
        const float* hp = g_h[t & 1];
        float* hc = g_h[(t + 1) & 1];

        // ============ Phase A: GRU gates (1 batch/thread, scalar) ==========
        if (bid < 147) {
            const int c0 = bid * 7;
            float aR[7], aU[7], aN[7];
            #pragma unroll
            for (int u = 0; u < 7; ++u) { aR[u]=0.f; aU[u]=0.f; aN[u]=0.f; }

            auto stageA = [&](int ct, int stg) {
                float* sx = sm + stg * STGF;
                float* sw = sx + 8448;
                if (ct == 0) {
                    cpacg(sx + xr * XST + xc,        g_z + xr * Sv + xc);
                    cpacg(sx + (xr+32) * XST + xc,   g_z + (xr+32) * Sv + xc);
                } else if (ct == 1) {
                    if (tid < 512) {
                        if (t > 0) cpacg(sx + ab * XST + aq,
                                         action + ((size_t)ab * Tv + (t-1)) * ACTv + aq);
                        else *(float4*)(sx + ab * XST + aq) = make_float4(0.f,0.f,0.f,0.f);
                    }
                } else {
                    cpacg(sx + xr * XST + xc,      hp + (size_t)xr * Hv + (ct-2) * KC + xc);
                    cpacg(sx + (xr+32) * XST + xc, hp + (size_t)(xr+32) * Hv + (ct-2) * KC + xc);
                }
                if (ct == 1) {
                    if (tid < 168) {
                        int r = tid >> 3, q = (tid & 7) * 4;
                        int g = r / 7, uu = r - g * 7;
                        int grow = g * Hv + min(c0 + uu, Hv - 1);
                        cpacg(sw + r * KC + q, w_ih + (size_t)grow * 160 + 128 + q);
                    }
                } else if (tid < 672) {
                    int r = tid >> 5, q = (tid & 31) * 4;
                    int g = r / 7, uu = r - g * 7;
                    int grow = g * Hv + min(c0 + uu, Hv - 1);
                    const float* src = (ct == 0)
                        ? w_ih + (size_t)grow * 160 + q
                        : w_hh + (size_t)grow * Hv + (ct-2) * KC + q;
                    cpacg(sw + r * KC + q, src);
                }
            };

            stageA(0, 0); CPCOMMIT(); stageA(1, 1); CPCOMMIT();
            for (int ct = 0; ct < 10; ++ct) {
                const int stg = ct % 3;
                CPWAIT1();
                __syncthreads();
                const float* sx = sm + stg * STGF;
                const float* sw = sx + 8448;
                const float* xrow = sx + bl * XST;
                if (ct == 1) {
                    const int kb = sg * 2;
                    float2 x2 = *(const float2*)(xrow + kb);
                    #pragma unroll
                    for (int u = 0; u < 7; ++u) {
                        float2 w;
                        w = *(const float2*)(sw + u*KC + kb);
                        aR[u] = fmaf(x2.x, w.x, fmaf(x2.y, w.y, aR[u]));
                        w = *(const float2*)(sw + (7+u)*KC + kb);
                        aU[u] = fmaf(x2.x, w.x, fmaf(x2.y, w.y, aU[u]));
                        w = *(const float2*)(sw + (14+u)*KC + kb);
                        aN[u] = fmaf(x2.x, w.x, fmaf(x2.y, w.y, aN[u]));
                    }
                } else {
                    const int kb = sg * 8;
                    #pragma unroll
                    for (int kk = 0; kk < 8; kk += 4) {
                        float4 x4 = *(const float4*)(xrow + kb + kk);
                        #pragma unroll
                        for (int u = 0; u < 7; ++u) {
                            float4 w;
                            w = *(const float4*)(sw + u*KC + kb + kk);
                            aR[u] = fmaf(x4.x, w.x, aR[u]); aR[u] = fmaf(x4.y, w.y, aR[u]);
                            aR[u] = fmaf(x4.z, w.z, aR[u]); aR[u] = fmaf(x4.w, w.w, aR[u]);
                            w = *(const float4*)(sw + (7+u)*KC + kb + kk);
                            aU[u] = fmaf(x4.x, w.x, aU[u]); aU[u] = fmaf(x4.y, w.y, aU[u]);
                            aU[u] = fmaf(x4.z, w.z, aU[u]); aU[u] = fmaf(x4.w, w.w, aU[u]);
                            w = *(const float4*)(sw + (14+u)*KC + kb + kk);
                            aN[u] = fmaf(x4.x, w.x, aN[u]); aN[u] = fmaf(x4.y, w.y, aN[u]);
                            aN[u] = fmaf(x4.z, w.z, aN[u]); aN[u] = fmaf(x4.w, w.w, aN[u]);
                        }
                    }
                }
                if (ct == 1) {      // retire n-gate x-side partials
                    #pragma unroll
                    for (int u = 0; u < 7; ++u) {
                        s_nx[(u*64 + bl) * RST + sg] = aN[u];
                        aN[u] = 0.f;
                    }
                }
                if (ct + 2 < 10) stageA(ct + 2, (ct + 2) % 3);
                CPCOMMIT();
            }
            __syncthreads();

            // pass 1: reduce R,U
            #pragma unroll
            for (int u = 0; u < 7; ++u) {
                s_red[(u*64 + bl)     * RST + sg] = aR[u];
                s_red[((7+u)*64 + bl) * RST + sg] = aU[u];
            }
            __syncthreads();
            float sR = 0.f, sU = 0.f;
            if (tid < 448) {
                const int u = tid >> 6, bi = tid & 63;
                #pragma unroll
                for (int s2 = 0; s2 < 16; ++s2) {
                    sR += s_red[(u*64 + bi) * RST + s2];
                    sU += s_red[((7+u)*64 + bi) * RST + s2];
                }
            }
            __syncthreads();
            // pass 2: reduce NH + pointwise
            #pragma unroll
            for (int u = 0; u < 7; ++u)
                s_red[(u*64 + bl) * RST + sg] = aN[u];
            __syncthreads();
            if (tid < 448) {
                const int u = tid >> 6, bi = tid & 63;
                const int j = c0 + u;
                if (j < Hv) {
                    float sH = 0.f, sX = 0.f;
                    #pragma unroll
                    for (int s2 = 0; s2 < 16; ++s2) {
                        sH += s_red[(u*64 + bi) * RST + s2];
                        sX += s_nx[(u*64 + bi) * RST + s2];
                    }
                    const float km = s_keep[bi];
                    const float hm = __ldcg(&hp[bi * Hv + j]);
                    float r  = sigm(sR + __ldg(&b_ih[j])       + __ldg(&b_hh[j]));
                    float uu = sigm(sU + __ldg(&b_ih[Hv+j])    + __ldg(&b_hh[Hv+j]));
                    float n  = tanhf(sX + __ldg(&b_ih[2*Hv+j]) + r * (sH + __ldg(&b_hh[2*Hv+j])));
                    float hn = (1.f - uu) * n + uu * hm;
                    hc[bi * Hv + j] = hn * km;
                    o_h[((size_t)bi * Tv + t) * Hv + j] = hn;
                }
            }
        }
        gridbar();

        // ====== Phase B: posterior L1 + fused prior L1 (f32x2) =============
        if (bid < 147) {
            const int c0q = bid * 7, c0p = bid * 4;
            const bool hasP = (bid < 128);
            ull aQ[7], aP[4];
            #pragma unroll
            for (int r = 0; r < 7; ++r) aQ[r] = 0ull;
            #pragma unroll
            for (int r = 0; r < 4; ++r) aP[r] = 0ull;

            auto stageB = [&](int ct, int stg) {
                float* sx = sm + stg * STGF;
                float* sw = sx + 8448;
                const float* s0 = (ct < 8)
                    ? hc + (size_t)xr * Hv + ct * KC + xc
                    : obs + ((size_t)xr * Tv + t) * OBSv + (ct-8) * KC + xc;
                const float* s1 = (ct < 8)
                    ? hc + (size_t)(xr+32) * Hv + ct * KC + xc
                    : obs + ((size_t)(xr+32) * Tv + t) * OBSv + (ct-8) * KC + xc;
                cpacg(sx + xr * XST + xc, s0);
                cpacg(sx + (xr+32) * XST + xc, s1);
                if (tid < 352) {
                    int r = tid >> 5, q = (tid & 31) * 4;
                    if (r < 7)
                        cpacg(sw + r * KC + q, qw1 + (size_t)min(c0q + r, 1023) * 2048 + ct * KC + q);
                    else if (hasP && ct < 8)
                        cpacg(sw + r * KC + q, pw1 + (size_t)(c0p + r - 7) * Hv + ct * KC + q);
                }
            };

            stageB(0, 0); CPCOMMIT(); stageB(1, 1); CPCOMMIT();
            for (int ct = 0; ct < 16; ++ct) {
                const int stg = ct % 3;
                CPWAIT1();
                __syncthreads();
                const float* sx = sm + stg * STGF;
                const float* sw = sx + 8448;
                const float* xrow = sx + bl * XST;
                const int kb = sg * 8;
                #pragma unroll
                for (int kk = 0; kk < 8; kk += 4) {
                    ulonglong2 xA = *(const ulonglong2*)(xrow + kb + kk);
                    #pragma unroll
                    for (int r = 0; r < 7; ++r) {
                        ulonglong2 w = *(const ulonglong2*)(sw + r*KC + kb + kk);
                        ffma2(aQ[r], xA.x, w.x); ffma2(aQ[r], xA.y, w.y);
                    }
                    if (hasP && ct < 8) {
                        #pragma unroll
                        for (int r = 0; r < 4; ++r) {
                            ulonglong2 w = *(const ulonglong2*)(sw + (7+r)*KC + kb + kk);
                            ffma2(aP[r], xA.x, w.x); ffma2(aP[r], xA.y, w.y);
                        }
                    }
                }
                if (ct + 2 < 16) stageB(ct + 2, (ct + 2) % 3);
                CPCOMMIT();
            }
            __syncthreads();

            #pragma unroll
            for (int r = 0; r < 7; ++r)
                s_red[(r*64 + bl) * RST + sg] = foldu(aQ[r]);
            #pragma unroll
            for (int r = 0; r < 4; ++r)
                s_red[((7+r)*64 + bl) * RST + sg] = foldu(aP[r]);
            __syncthreads();
            if (tid < 704) {
                const int r = tid >> 6, bi = tid & 63;
                float sum = 0.f;
                #pragma unroll
                for (int s2 = 0; s2 < 16; ++s2) sum += s_red[(r*64 + bi) * RST + s2];
                if (r < 7) {
                    int col = c0q + r;
                    if (col < 1024) g_a2[bi * 1024 + col] = fmaxf(sum + __ldg(&qb1[col]), 0.f);
                } else if (hasP) {
                    int col = c0p + (r - 7);
                    g_a1[bi * 512 + col] = fmaxf(sum + __ldg(&pb1[col]), 0.f);
                }
            }
        }
        gridbar();

        // ====== Phase C: heads (f32x2). blocks 0..31 prior, 32..95 post ====
        {
            const bool isPr = (bid < 32);
            const bool isPo = (bid >= 32 && bid < 96);
            if (isPr || isPo) {
                const int NR  = isPr ? 8 : 4;
                const int NCH = isPr ? 4 : 8;
                const int s0  = isPr ? bid * 4 : (bid - 32) * 2;
                const int Kc  = isPr ? 512 : 1024;
                const float* W2 = isPr ? pw2 : qw2;
                const float* B2 = isPr ? pb2 : qb2;
                const float* Ain = isPr ? g_a1 : g_a2;
                ull aC[8];
                #pragma unroll
                for (int r = 0; r < 8; ++r) aC[r] = 0ull;

                auto stageC = [&](int ct, int stg) {
                    float* sx = sm + stg * STGF;
                    float* sw = sx + 8448;
                    cpacg(sx + xr * XST + xc,      Ain + (size_t)xr * Kc + ct * KC + xc);
                    cpacg(sx + (xr+32) * XST + xc, Ain + (size_t)(xr+32) * Kc + ct * KC + xc);
                    if (tid < NR * 32) {
                        int r = tid >> 5, q = (tid & 31) * 4;
                        int grow = (r & 1) * Sv + s0 + (r >> 1);
                        cpacg(sw + r * KC + q, W2 + (size_t)grow * Kc + ct * KC + q);
                    }
                };

                stageC(0, 0); CPCOMMIT(); stageC(1, 1); CPCOMMIT();
                for (int ct = 0; ct < NCH; ++ct) {
                    const int stg = ct % 3;
                    CPWAIT1();
                    __syncthreads();
                    const float* sx = sm + stg * STGF;
                    const float* sw = sx + 8448;
                    const float* xrow = sx + bl * XST;
                    const int kb = sg * 8;
                    #pragma unroll
                    for (int kk = 0; kk < 8; kk += 4) {
                        ulonglong2 xA = *(const ulonglong2*)(xrow + kb + kk);
                        if (isPr) {
                            #pragma unroll
                            for (int r = 0; r < 8; ++r) {
                                ulonglong2 w = *(const ulonglong2*)(sw + r*KC + kb + kk);
                                ffma2(aC[r], xA.x, w.x); ffma2(aC[r], xA.y, w.y);
                            }
                        } else {
                            #pragma unroll
                            for (int r = 0; r < 4; ++r) {
                                ulonglong2 w = *(const ulonglong2*)(sw + r*KC + kb + kk);
                                ffma2(aC[r], xA.x, w.x); ffma2(aC[r], xA.y, w.y);
                            }
                        }
                    }
                    if (ct + 2 < NCH) stageC(ct + 2, (ct + 2) % 3);
                    CPCOMMIT();
                }
                __syncthreads();

                #pragma unroll
                for (int r = 0; r < 8; ++r)
                    if (r < NR) s_red[(r*64 + bl) * RST + sg] = foldu(aC[r]);
                __syncthreads();

                float v = 0.f; int rr = 0, bi = 0, s = 0, role = 0;
                const bool fin = (tid < NR * 64);
                if (fin) {
                    rr = tid >> 6; bi = tid & 63;
                    role = rr & 1; s = s0 + (rr >> 1);
                    float sum = 0.f;
                    #pragma unroll
                    for (int s2 = 0; s2 < 16; ++s2) sum += s_red[(rr*64 + bi) * RST + s2];
                    v = sum + __ldg(&B2[role * Sv + s]);
                    const size_t oidx = ((size_t)bi * Sv + s) * Tv + t;
                    if (isPr) {
                        if (role == 0) o_pm[oidx] = v;
                        else           o_ps[oidx] = sftp(v) + 1e-6f;
                    } else if (role == 1) {
                        float sd = sftp(v) + 1e-6f;
                        o_qs[oidx] = sd;
                        s_ex[(rr >> 1) * 64 + bi] = sd;
                    }
                }
                __syncthreads();
                if (isPo && fin && role == 0) {
                    float sd = s_ex[(rr >> 1) * 64 + bi];
                    float nz = __ldg(&noise[((size_t)bi * Tv + t) * Sv + s]);
                    float z  = v + sd * nz;
                    g_z[bi * Sv + s] = z * s_keep[bi];
                    o_z[((size_t)bi * Tv + t) * Sv + s] = z;
                    o_qm[((size_t)bi * Sv + s) * Tv + t] = v;
                }
            }
        }
        gridbar();
    }
}

extern "C" void kernel_launch(void* const* d_in, const int* in_sizes, int n_in,
                              void* d_out, int out_size) {
    (void)in_sizes; (void)n_in; (void)out_size;
    cudaFuncSetAttribute(rssm_kernel, cudaFuncAttributeMaxDynamicSharedMemorySize, SMEM_BYTES);
    rssm_kernel<<<NBLK, NTHR, SMEM_BYTES>>>(
        (const float*)d_in[0],  (const float*)d_in[1],
        (const unsigned char*)d_in[2], (const float*)d_in[3],
        (const float*)d_in[4],  (const float*)d_in[5],
        (const float*)d_in[6],  (const float*)d_in[7],
        (const float*)d_in[8],  (const float*)d_in[9],
        (const float*)d_in[10], (const float*)d_in[11],
        (const float*)d_in[12], (const float*)d_in[13],
        (const float*)d_in[14], (const float*)d_in[15],
        (float*)d_out);
}